// round 1
// baseline (speedup 1.0000x reference)
#include <cuda_runtime.h>

#define DEV_INLINE __device__ __forceinline__

constexpr int B_  = 8;
constexpr int TQ  = 256;
constexpr int TV  = 512;
constexpr int D_  = 256;
constexpr float SCALE2 = 2.8853900817779268f;   // 2*log2(e): e^{2x} = 2^{SCALE2*x}
constexpr float LOG2E  = 1.4426950408889634f;

// Scratch (device globals — no allocation allowed)
__device__ float g_qproj[B_ * TQ * D_];   // (query@W1 + b1) * SCALE2
__device__ float g_vproj[B_ * TV * D_];   // (value@W2 + b2) * SCALE2
__device__ float g_score[B_ * TQ * TV];   // scores, then alignment in-place

DEV_INLINE float fast_ex2(float x) { float y; asm("ex2.approx.f32 %0, %1;" : "=f"(y) : "f"(x)); return y; }
DEV_INLINE float fast_rcp(float x) { float y; asm("rcp.approx.f32 %0, %1;" : "=f"(y) : "f"(x)); return y; }
// r = 1/(1+e^{2x_true}) where x is prescaled by 2*log2(e); tanh = 1 - 2r
DEV_INLINE float sig2(float x) { return fast_rcp(1.0f + fast_ex2(x)); }

// ---------------------------------------------------------------------------
// K1: projection GEMM  P[m][e] = (sum_d X[m][d]*W[d][e] + b[e]) * SCALE2
// Tile 64x64, BK=16, 256 threads, 4x4 per thread.
// ---------------------------------------------------------------------------
__global__ __launch_bounds__(256) void proj_kernel(
    const float* __restrict__ X, const float* __restrict__ W,
    const float* __restrict__ bias, float* __restrict__ P)
{
    __shared__ float sAT[16][64];   // A transposed: [k][m]
    __shared__ float sB[16][64];    // [k][n]
    const int tid = threadIdx.x;
    const int mb = blockIdx.y * 64;
    const int nb = blockIdx.x * 64;
    const int tm = tid >> 4, tn = tid & 15;

    const int arow = tid >> 2, akv = tid & 3;    // A: one float4 per thread per k-tile
    const int brow = tid >> 4, bcv = tid & 15;   // B: one float4 per thread per k-tile

    float acc[4][4] = {};

    for (int kt = 0; kt < D_; kt += 16) {
        float4 av = *(const float4*)(X + (mb + arow) * D_ + kt + akv * 4);
        float4 bv = *(const float4*)(W + (kt + brow) * D_ + nb + bcv * 4);
        __syncthreads();
        sAT[akv*4+0][arow] = av.x; sAT[akv*4+1][arow] = av.y;
        sAT[akv*4+2][arow] = av.z; sAT[akv*4+3][arow] = av.w;
        *(float4*)&sB[brow][bcv*4] = bv;
        __syncthreads();
        #pragma unroll
        for (int k = 0; k < 16; k++) {
            float a[4];
            #pragma unroll
            for (int i = 0; i < 4; i++) a[i] = sAT[k][tm*4 + i];
            float4 bq = *(float4*)&sB[k][tn*4];
            #pragma unroll
            for (int i = 0; i < 4; i++) {
                acc[i][0] += a[i] * bq.x; acc[i][1] += a[i] * bq.y;
                acc[i][2] += a[i] * bq.z; acc[i][3] += a[i] * bq.w;
            }
        }
    }
    float4 bias4 = *(const float4*)(bias + nb + tn*4);
    #pragma unroll
    for (int i = 0; i < 4; i++) {
        float4 o;
        o.x = (acc[i][0] + bias4.x) * SCALE2;
        o.y = (acc[i][1] + bias4.y) * SCALE2;
        o.z = (acc[i][2] + bias4.z) * SCALE2;
        o.w = (acc[i][3] + bias4.w) * SCALE2;
        *(float4*)(P + (mb + tm*4 + i) * D_ + nb + tn*4) = o;
    }
}

// ---------------------------------------------------------------------------
// K2: score[b][qi][jj] = D - 2 * sum_d 1/(1+2^{q'[qi][d]+v'[jj][d]})
// Tile: 64 qi x 32 jj per block, 256 threads, 4x2 pairs/thread, DK=32 chunks.
// Smem tiles XOR-swizzled at float4 granularity.
// ---------------------------------------------------------------------------
__global__ __launch_bounds__(256) void score_kernel()
{
    constexpr int DK = 32;
    __shared__ float4 sQ[64 * 8];   // pos = r*8 + (vec ^ (r&7))
    __shared__ float4 sV[32 * 8];

    const int tid = threadIdx.x;
    const int b   = blockIdx.y;
    const int qt  = blockIdx.x >> 4;     // 0..3  (TQ/64)
    const int jt  = blockIdx.x & 15;     // 0..15 (TV/32)
    const int qbase = qt * 64, jbase = jt * 32;
    const float* qp = g_qproj + (b * TQ + qbase) * D_;
    const float* vp = g_vproj + (b * TV + jbase) * D_;
    const int tq = tid >> 4, tj = tid & 15;

    float acc[4][2] = {};

    for (int dc = 0; dc < D_; dc += DK) {
        __syncthreads();
        #pragma unroll
        for (int i = 0; i < 2; i++) {          // 64 rows x 8 vecs of Q
            int idx = i * 256 + tid;
            int r = idx >> 3, vec = idx & 7;
            sQ[r*8 + (vec ^ (r & 7))] = *(const float4*)(qp + r * D_ + dc + vec * 4);
        }
        {                                       // 32 rows x 8 vecs of V
            int r = tid >> 3, vec = tid & 7;
            sV[r*8 + (vec ^ (r & 7))] = *(const float4*)(vp + r * D_ + dc + vec * 4);
        }
        __syncthreads();

        #pragma unroll
        for (int vec = 0; vec < 8; vec++) {
            float4 qv[4], vv[2];
            #pragma unroll
            for (int a = 0; a < 4; a++) { int r = a*16 + tq; qv[a] = sQ[r*8 + (vec ^ (r & 7))]; }
            #pragma unroll
            for (int bb = 0; bb < 2; bb++) { int r = bb*16 + tj; vv[bb] = sV[r*8 + (vec ^ (r & 7))]; }
            #pragma unroll
            for (int a = 0; a < 4; a++)
                #pragma unroll
                for (int bb = 0; bb < 2; bb++) {
                    float s0 = sig2(qv[a].x + vv[bb].x);
                    float s1 = sig2(qv[a].y + vv[bb].y);
                    float s2 = sig2(qv[a].z + vv[bb].z);
                    float s3 = sig2(qv[a].w + vv[bb].w);
                    acc[a][bb] += (s0 + s1) + (s2 + s3);
                }
        }
    }

    #pragma unroll
    for (int a = 0; a < 4; a++)
        #pragma unroll
        for (int bb = 0; bb < 2; bb++) {
            int qi = qbase + a*16 + tq;
            int jj = jbase + bb*16 + tj;
            g_score[(b * TQ + qi) * TV + jj] = (float)D_ - 2.0f * acc[a][bb];
        }
}

// ---------------------------------------------------------------------------
// K3: row softmax over TV=512, in-place into g_score (alignment) and write
// transposed alignment_t output [B, TV, TQ]. One block per (b, qi).
// ---------------------------------------------------------------------------
__global__ __launch_bounds__(128) void softmax_kernel(float* __restrict__ out_at)
{
    const int row = blockIdx.x;               // 0..B*TQ-1
    const int b = row >> 8, qi = row & 255;
    float* s = g_score + row * TV;
    const int tid = threadIdx.x;              // 128 threads, 4 elems each

    float4 v = *(const float4*)(s + tid * 4);
    float m = fmaxf(fmaxf(v.x, v.y), fmaxf(v.z, v.w));
    #pragma unroll
    for (int o = 16; o; o >>= 1) m = fmaxf(m, __shfl_xor_sync(0xffffffffu, m, o));
    __shared__ float redm[4];
    if ((tid & 31) == 0) redm[tid >> 5] = m;
    __syncthreads();
    m = fmaxf(fmaxf(redm[0], redm[1]), fmaxf(redm[2], redm[3]));

    float e0 = fast_ex2((v.x - m) * LOG2E);
    float e1 = fast_ex2((v.y - m) * LOG2E);
    float e2 = fast_ex2((v.z - m) * LOG2E);
    float e3 = fast_ex2((v.w - m) * LOG2E);
    float ssum = (e0 + e1) + (e2 + e3);
    #pragma unroll
    for (int o = 16; o; o >>= 1) ssum += __shfl_xor_sync(0xffffffffu, ssum, o);
    __shared__ float reds[4];
    if ((tid & 31) == 0) reds[tid >> 5] = ssum;
    __syncthreads();
    ssum = (reds[0] + reds[1]) + (reds[2] + reds[3]);

    float inv = 1.0f / ssum;
    float a0 = e0 * inv, a1 = e1 * inv, a2 = e2 * inv, a3 = e3 * inv;
    *(float4*)(s + tid * 4) = make_float4(a0, a1, a2, a3);

    const int jb = tid * 4;
    out_at[(b * TV + jb + 0) * TQ + qi] = a0;
    out_at[(b * TV + jb + 1) * TQ + qi] = a1;
    out_at[(b * TV + jb + 2) * TQ + qi] = a2;
    out_at[(b * TV + jb + 3) * TQ + qi] = a3;
}

// ---------------------------------------------------------------------------
// K4: context[b] = alignment[b] (256x512) @ value[b] (512x256), written into
// out[b][qi][0:256] with row stride 2D. Tile 64x64, BK=16.
// ---------------------------------------------------------------------------
__global__ __launch_bounds__(256) void context_kernel(
    const float* __restrict__ value, float* __restrict__ out)
{
    __shared__ float sAT[16][64];
    __shared__ float sB[16][64];
    const int tid = threadIdx.x;
    const int b  = blockIdx.z;
    const int mb = blockIdx.y * 64;
    const int nb = blockIdx.x * 64;
    const float* A = g_score + b * TQ * TV;      // alignment
    const float* V = value + b * TV * D_;
    float* C = out + b * TQ * (2 * D_);
    const int tm = tid >> 4, tn = tid & 15;
    const int arow = tid >> 2, akv = tid & 3;
    const int brow = tid >> 4, bcv = tid & 15;

    float acc[4][4] = {};

    for (int kt = 0; kt < TV; kt += 16) {
        float4 av = *(const float4*)(A + (mb + arow) * TV + kt + akv * 4);
        float4 bv = *(const float4*)(V + (kt + brow) * D_ + nb + bcv * 4);
        __syncthreads();
        sAT[akv*4+0][arow] = av.x; sAT[akv*4+1][arow] = av.y;
        sAT[akv*4+2][arow] = av.z; sAT[akv*4+3][arow] = av.w;
        *(float4*)&sB[brow][bcv*4] = bv;
        __syncthreads();
        #pragma unroll
        for (int k = 0; k < 16; k++) {
            float a[4];
            #pragma unroll
            for (int i = 0; i < 4; i++) a[i] = sAT[k][tm*4 + i];
            float4 bq = *(float4*)&sB[k][tn*4];
            #pragma unroll
            for (int i = 0; i < 4; i++) {
                acc[i][0] += a[i] * bq.x; acc[i][1] += a[i] * bq.y;
                acc[i][2] += a[i] * bq.z; acc[i][3] += a[i] * bq.w;
            }
        }
    }
    #pragma unroll
    for (int i = 0; i < 4; i++) {
        float4 o = make_float4(acc[i][0], acc[i][1], acc[i][2], acc[i][3]);
        *(float4*)(C + (mb + tm*4 + i) * (2 * D_) + nb + tn*4) = o;
    }
}

// ---------------------------------------------------------------------------
// K5: out[b][qi][D:2D] = query[b][qi][:]
// ---------------------------------------------------------------------------
__global__ __launch_bounds__(256) void copy_query_kernel(
    const float* __restrict__ query, float* __restrict__ out)
{
    int g = blockIdx.x * 256 + threadIdx.x;      // over B*TQ*D/4 float4s
    int row = g >> 6, vec = g & 63;              // 64 float4s per row
    ((float4*)out)[row * 128 + 64 + vec] = ((const float4*)query)[g];
}

// ---------------------------------------------------------------------------
extern "C" void kernel_launch(void* const* d_in, const int* in_sizes, int n_in,
                              void* d_out, int out_size)
{
    const float* query = (const float*)d_in[0];   // [8,256,256]
    const float* value = (const float*)d_in[1];   // [8,512,256]
    const float* W1    = (const float*)d_in[2];   // [256,256]
    const float* b1    = (const float*)d_in[3];   // [256]
    const float* W2    = (const float*)d_in[4];   // [256,256]
    const float* b2    = (const float*)d_in[5];   // [256]
    float* out = (float*)d_out;                   // [8*256*512 ctx] + [8*512*256 align_t]

    void *qp_, *vp_;
    cudaGetSymbolAddress(&qp_, g_qproj);
    cudaGetSymbolAddress(&vp_, g_vproj);

    proj_kernel<<<dim3(4, 32), 256>>>(query, W1, b1, (float*)qp_);   // 2048x256
    proj_kernel<<<dim3(4, 64), 256>>>(value, W2, b2, (float*)vp_);   // 4096x256
    score_kernel<<<dim3(64, 8), 256>>>();
    softmax_kernel<<<B_ * TQ, 128>>>(out + B_ * TQ * 2 * D_);
    context_kernel<<<dim3(4, 4, 8), 256>>>(value, out);
    copy_query_kernel<<<512, 256>>>(query, out);
}

// round 2
// speedup vs baseline: 1.2109x; 1.2109x over previous
#include <cuda_runtime.h>

#define DEV_INLINE __device__ __forceinline__

constexpr int B_  = 8;
constexpr int TQ  = 256;
constexpr int TV  = 512;
constexpr int D_  = 256;
constexpr float SCALE2 = 2.8853900817779268f;   // 2*log2(e): e^{2x} = 2^{SCALE2*x}
constexpr float LOG2E  = 1.4426950408889634f;

// Scratch (device globals — no allocation allowed)
__device__ float g_qproj[B_ * TQ * D_];   // (query@W1 + b1) * SCALE2
__device__ float g_vproj[B_ * TV * D_];   // (value@W2 + b2) * SCALE2
__device__ float g_score[B_ * TQ * TV];   // scores, then alignment in-place

DEV_INLINE float fast_ex2(float x) { float y; asm("ex2.approx.f32 %0, %1;" : "=f"(y) : "f"(x)); return y; }
DEV_INLINE float fast_rcp(float x) { float y; asm("rcp.approx.f32 %0, %1;" : "=f"(y) : "f"(x)); return y; }

// FMA-pipe reciprocal: magic-constant seed + 2 Newton steps (rel err ~1.3e-5).
DEV_INLINE float newton_rcp(float z) {
    float y = __uint_as_float(0x7EF311C3u - __float_as_uint(z));
    y = y * fmaf(-z, y, 2.0f);
    y = y * fmaf(-z, y, 2.0f);
    return y;
}

// sum_{i=0..3} 1/(1+2^{q_i+v_i})  with ONE division per 4 lanes.
// use_mufu selects rcp.approx (MUFU pipe) vs Newton (FMA pipe) for balance.
template <bool USE_MUFU>
DEV_INLINE float quad_sig(float4 q, float4 v) {
    float z0 = 1.0f + fast_ex2(q.x + v.x);
    float z1 = 1.0f + fast_ex2(q.y + v.y);
    float z2 = 1.0f + fast_ex2(q.z + v.z);
    float z3 = 1.0f + fast_ex2(q.w + v.w);
    float p12 = z0 * z1;
    float p34 = z2 * z3;
    float num = fmaf(p12, z2 + z3, p34 * (z0 + z1));
    float den = p12 * p34;
    float r = USE_MUFU ? fast_rcp(den) : newton_rcp(den);
    return num * r;
}

// ---------------------------------------------------------------------------
// K1: projection GEMM  P[m][e] = (sum_d X[m][d]*W[d][e] + b[e]) * SCALE2
// ---------------------------------------------------------------------------
__global__ __launch_bounds__(256) void proj_kernel(
    const float* __restrict__ X, const float* __restrict__ W,
    const float* __restrict__ bias, float* __restrict__ P)
{
    __shared__ float sAT[16][64];   // A transposed: [k][m]
    __shared__ float sB[16][64];    // [k][n]
    const int tid = threadIdx.x;
    const int mb = blockIdx.y * 64;
    const int nb = blockIdx.x * 64;
    const int tm = tid >> 4, tn = tid & 15;

    const int arow = tid >> 2, akv = tid & 3;
    const int brow = tid >> 4, bcv = tid & 15;

    float acc[4][4] = {};

    for (int kt = 0; kt < D_; kt += 16) {
        float4 av = *(const float4*)(X + (mb + arow) * D_ + kt + akv * 4);
        float4 bv = *(const float4*)(W + (kt + brow) * D_ + nb + bcv * 4);
        __syncthreads();
        sAT[akv*4+0][arow] = av.x; sAT[akv*4+1][arow] = av.y;
        sAT[akv*4+2][arow] = av.z; sAT[akv*4+3][arow] = av.w;
        *(float4*)&sB[brow][bcv*4] = bv;
        __syncthreads();
        #pragma unroll
        for (int k = 0; k < 16; k++) {
            float a[4];
            #pragma unroll
            for (int i = 0; i < 4; i++) a[i] = sAT[k][tm*4 + i];
            float4 bq = *(float4*)&sB[k][tn*4];
            #pragma unroll
            for (int i = 0; i < 4; i++) {
                acc[i][0] += a[i] * bq.x; acc[i][1] += a[i] * bq.y;
                acc[i][2] += a[i] * bq.z; acc[i][3] += a[i] * bq.w;
            }
        }
    }
    float4 bias4 = *(const float4*)(bias + nb + tn*4);
    #pragma unroll
    for (int i = 0; i < 4; i++) {
        float4 o;
        o.x = (acc[i][0] + bias4.x) * SCALE2;
        o.y = (acc[i][1] + bias4.y) * SCALE2;
        o.z = (acc[i][2] + bias4.z) * SCALE2;
        o.w = (acc[i][3] + bias4.w) * SCALE2;
        *(float4*)(P + (mb + tm*4 + i) * D_ + nb + tn*4) = o;
    }
}

// ---------------------------------------------------------------------------
// K2: score[b][qi][jj] = D - 2 * sum_d 1/(1+2^{q'[qi][d]+v'[jj][d]})
// Quad-rational trick: one division per float4 of d. Division alternates
// MUFU rcp / FMA-Newton per vec iteration to balance pipes.
// ---------------------------------------------------------------------------
__global__ __launch_bounds__(256) void score_kernel()
{
    constexpr int DK = 32;
    __shared__ float4 sQ[64 * 8];   // pos = r*8 + (vec ^ (r&7))
    __shared__ float4 sV[32 * 8];

    const int tid = threadIdx.x;
    const int b   = blockIdx.y;
    const int qt  = blockIdx.x >> 4;     // 0..3  (TQ/64)
    const int jt  = blockIdx.x & 15;     // 0..15 (TV/32)
    const int qbase = qt * 64, jbase = jt * 32;
    const float* qp = g_qproj + (b * TQ + qbase) * D_;
    const float* vp = g_vproj + (b * TV + jbase) * D_;
    const int tq = tid >> 4, tj = tid & 15;

    float acc[4][2] = {};

    for (int dc = 0; dc < D_; dc += DK) {
        __syncthreads();
        #pragma unroll
        for (int i = 0; i < 2; i++) {          // 64 rows x 8 vecs of Q
            int idx = i * 256 + tid;
            int r = idx >> 3, vec = idx & 7;
            sQ[r*8 + (vec ^ (r & 7))] = *(const float4*)(qp + r * D_ + dc + vec * 4);
        }
        {                                       // 32 rows x 8 vecs of V
            int r = tid >> 3, vec = tid & 7;
            sV[r*8 + (vec ^ (r & 7))] = *(const float4*)(vp + r * D_ + dc + vec * 4);
        }
        __syncthreads();

        #pragma unroll
        for (int vec = 0; vec < 8; vec++) {
            float4 qv[4], vv[2];
            #pragma unroll
            for (int a = 0; a < 4; a++) { int r = a*16 + tq; qv[a] = sQ[r*8 + (vec ^ (r & 7))]; }
            #pragma unroll
            for (int bb = 0; bb < 2; bb++) { int r = bb*16 + tj; vv[bb] = sV[r*8 + (vec ^ (r & 7))]; }
            #pragma unroll
            for (int a = 0; a < 4; a++)
                #pragma unroll
                for (int bb = 0; bb < 2; bb++) {
                    if (vec & 1)
                        acc[a][bb] += quad_sig<false>(qv[a], vv[bb]);
                    else
                        acc[a][bb] += quad_sig<true>(qv[a], vv[bb]);
                }
        }
    }

    #pragma unroll
    for (int a = 0; a < 4; a++)
        #pragma unroll
        for (int bb = 0; bb < 2; bb++) {
            int qi = qbase + a*16 + tq;
            int jj = jbase + bb*16 + tj;
            g_score[(b * TQ + qi) * TV + jj] = (float)D_ - 2.0f * acc[a][bb];
        }
}

// ---------------------------------------------------------------------------
// K3: row softmax over TV=512, in-place alignment + transposed output.
// ---------------------------------------------------------------------------
__global__ __launch_bounds__(128) void softmax_kernel(float* __restrict__ out_at)
{
    const int row = blockIdx.x;               // 0..B*TQ-1
    const int b = row >> 8, qi = row & 255;
    float* s = g_score + row * TV;
    const int tid = threadIdx.x;              // 128 threads, 4 elems each

    float4 v = *(const float4*)(s + tid * 4);
    float m = fmaxf(fmaxf(v.x, v.y), fmaxf(v.z, v.w));
    #pragma unroll
    for (int o = 16; o; o >>= 1) m = fmaxf(m, __shfl_xor_sync(0xffffffffu, m, o));
    __shared__ float redm[4];
    if ((tid & 31) == 0) redm[tid >> 5] = m;
    __syncthreads();
    m = fmaxf(fmaxf(redm[0], redm[1]), fmaxf(redm[2], redm[3]));

    float e0 = fast_ex2((v.x - m) * LOG2E);
    float e1 = fast_ex2((v.y - m) * LOG2E);
    float e2 = fast_ex2((v.z - m) * LOG2E);
    float e3 = fast_ex2((v.w - m) * LOG2E);
    float ssum = (e0 + e1) + (e2 + e3);
    #pragma unroll
    for (int o = 16; o; o >>= 1) ssum += __shfl_xor_sync(0xffffffffu, ssum, o);
    __shared__ float reds[4];
    if ((tid & 31) == 0) reds[tid >> 5] = ssum;
    __syncthreads();
    ssum = (reds[0] + reds[1]) + (reds[2] + reds[3]);

    float inv = 1.0f / ssum;
    float a0 = e0 * inv, a1 = e1 * inv, a2 = e2 * inv, a3 = e3 * inv;
    *(float4*)(s + tid * 4) = make_float4(a0, a1, a2, a3);

    const int jb = tid * 4;
    out_at[(b * TV + jb + 0) * TQ + qi] = a0;
    out_at[(b * TV + jb + 1) * TQ + qi] = a1;
    out_at[(b * TV + jb + 2) * TQ + qi] = a2;
    out_at[(b * TV + jb + 3) * TQ + qi] = a3;
}

// ---------------------------------------------------------------------------
// K4: context[b] = alignment[b] (256x512) @ value[b] (512x256)
// ---------------------------------------------------------------------------
__global__ __launch_bounds__(256) void context_kernel(
    const float* __restrict__ value, float* __restrict__ out)
{
    __shared__ float sAT[16][64];
    __shared__ float sB[16][64];
    const int tid = threadIdx.x;
    const int b  = blockIdx.z;
    const int mb = blockIdx.y * 64;
    const int nb = blockIdx.x * 64;
    const float* A = g_score + b * TQ * TV;      // alignment
    const float* V = value + b * TV * D_;
    float* C = out + b * TQ * (2 * D_);
    const int tm = tid >> 4, tn = tid & 15;
    const int arow = tid >> 2, akv = tid & 3;
    const int brow = tid >> 4, bcv = tid & 15;

    float acc[4][4] = {};

    for (int kt = 0; kt < TV; kt += 16) {
        float4 av = *(const float4*)(A + (mb + arow) * TV + kt + akv * 4);
        float4 bv = *(const float4*)(V + (kt + brow) * D_ + nb + bcv * 4);
        __syncthreads();
        sAT[akv*4+0][arow] = av.x; sAT[akv*4+1][arow] = av.y;
        sAT[akv*4+2][arow] = av.z; sAT[akv*4+3][arow] = av.w;
        *(float4*)&sB[brow][bcv*4] = bv;
        __syncthreads();
        #pragma unroll
        for (int k = 0; k < 16; k++) {
            float a[4];
            #pragma unroll
            for (int i = 0; i < 4; i++) a[i] = sAT[k][tm*4 + i];
            float4 bq = *(float4*)&sB[k][tn*4];
            #pragma unroll
            for (int i = 0; i < 4; i++) {
                acc[i][0] += a[i] * bq.x; acc[i][1] += a[i] * bq.y;
                acc[i][2] += a[i] * bq.z; acc[i][3] += a[i] * bq.w;
            }
        }
    }
    #pragma unroll
    for (int i = 0; i < 4; i++) {
        float4 o = make_float4(acc[i][0], acc[i][1], acc[i][2], acc[i][3]);
        *(float4*)(C + (mb + tm*4 + i) * (2 * D_) + nb + tn*4) = o;
    }
}

// ---------------------------------------------------------------------------
// K5: out[b][qi][D:2D] = query[b][qi][:]
// ---------------------------------------------------------------------------
__global__ __launch_bounds__(256) void copy_query_kernel(
    const float* __restrict__ query, float* __restrict__ out)
{
    int g = blockIdx.x * 256 + threadIdx.x;      // over B*TQ*D/4 float4s
    int row = g >> 6, vec = g & 63;              // 64 float4s per row
    ((float4*)out)[row * 128 + 64 + vec] = ((const float4*)query)[g];
}

// ---------------------------------------------------------------------------
extern "C" void kernel_launch(void* const* d_in, const int* in_sizes, int n_in,
                              void* d_out, int out_size)
{
    const float* query = (const float*)d_in[0];   // [8,256,256]
    const float* value = (const float*)d_in[1];   // [8,512,256]
    const float* W1    = (const float*)d_in[2];   // [256,256]
    const float* b1    = (const float*)d_in[3];   // [256]
    const float* W2    = (const float*)d_in[4];   // [256,256]
    const float* b2    = (const float*)d_in[5];   // [256]
    float* out = (float*)d_out;                   // [8*256*512 ctx] + [8*512*256 align_t]

    void *qp_, *vp_;
    cudaGetSymbolAddress(&qp_, g_qproj);
    cudaGetSymbolAddress(&vp_, g_vproj);

    proj_kernel<<<dim3(4, 32), 256>>>(query, W1, b1, (float*)qp_);   // 2048x256
    proj_kernel<<<dim3(4, 64), 256>>>(value, W2, b2, (float*)vp_);   // 4096x256
    score_kernel<<<dim3(64, 8), 256>>>();
    softmax_kernel<<<B_ * TQ, 128>>>(out + B_ * TQ * 2 * D_);
    context_kernel<<<dim3(4, 4, 8), 256>>>(value, out);
    copy_query_kernel<<<512, 256>>>(query, out);
}

// round 3
// speedup vs baseline: 1.2924x; 1.0673x over previous
#include <cuda_runtime.h>

#define DEV_INLINE __device__ __forceinline__
using u64 = unsigned long long;

constexpr int B_  = 8;
constexpr int TQ  = 256;
constexpr int TV  = 512;
constexpr int D_  = 256;
constexpr float SCALE2 = 2.8853900817779268f;   // 2*log2(e): e^{2x} = 2^{SCALE2*x}
constexpr float LOG2E  = 1.4426950408889634f;

// Scratch (device globals — no allocation allowed)
__device__ float g_qproj[B_ * TQ * D_];   // (query@W1 + b1) * SCALE2
__device__ float g_vproj[B_ * TV * D_];   // (value@W2 + b2) * SCALE2
__device__ float g_score[B_ * TQ * TV];   // scores, then alignment in-place

DEV_INLINE float fast_ex2(float x) { float y; asm("ex2.approx.f32 %0, %1;" : "=f"(y) : "f"(x)); return y; }

// ---- packed f32x2 helpers (Blackwell double-pumped fp32 pipe) ----
DEV_INLINE u64 pk2(float lo, float hi) { u64 r; asm("mov.b64 %0, {%1, %2};" : "=l"(r) : "f"(lo), "f"(hi)); return r; }
DEV_INLINE void upk2(u64 p, float& lo, float& hi) { asm("mov.b64 {%0, %1}, %2;" : "=f"(lo), "=f"(hi) : "l"(p)); }
DEV_INLINE u64 add2(u64 a, u64 b) { u64 r; asm("add.rn.f32x2 %0, %1, %2;" : "=l"(r) : "l"(a), "l"(b)); return r; }
DEV_INLINE u64 mul2(u64 a, u64 b) { u64 r; asm("mul.rn.f32x2 %0, %1, %2;" : "=l"(r) : "l"(a), "l"(b)); return r; }
DEV_INLINE u64 fma2(u64 a, u64 b, u64 c) { u64 r; asm("fma.rn.f32x2 %0, %1, %2, %3;" : "=l"(r) : "l"(a), "l"(b), "l"(c)); return r; }

// ---------------------------------------------------------------------------
// K1: projection GEMM  P[m][e] = (sum_d X[m][d]*W[d][e] + b[e]) * SCALE2
// f32x2 inner loop: acc pairs over adjacent rows.
// ---------------------------------------------------------------------------
__global__ __launch_bounds__(256) void proj_kernel(
    const float* __restrict__ X, const float* __restrict__ W,
    const float* __restrict__ bias, float* __restrict__ P)
{
    __shared__ float sAT[16][64];   // A transposed: [k][m]
    __shared__ float sB[16][64];    // [k][n]
    const int tid = threadIdx.x;
    const int mb = blockIdx.y * 64;
    const int nb = blockIdx.x * 64;
    const int tm = tid >> 4, tn = tid & 15;

    const int arow = tid >> 2, akv = tid & 3;
    const int brow = tid >> 4, bcv = tid & 15;

    u64 acc2[2][4] = {};   // acc2[ip][j] = (row 2ip, row 2ip+1) x col j

    for (int kt = 0; kt < D_; kt += 16) {
        float4 av = *(const float4*)(X + (mb + arow) * D_ + kt + akv * 4);
        float4 bv = *(const float4*)(W + (kt + brow) * D_ + nb + bcv * 4);
        __syncthreads();
        sAT[akv*4+0][arow] = av.x; sAT[akv*4+1][arow] = av.y;
        sAT[akv*4+2][arow] = av.z; sAT[akv*4+3][arow] = av.w;
        *(float4*)&sB[brow][bcv*4] = bv;
        __syncthreads();
        #pragma unroll
        for (int k = 0; k < 16; k++) {
            float2 a01 = *(const float2*)&sAT[k][tm*4];
            float2 a23 = *(const float2*)&sAT[k][tm*4 + 2];
            float4 bq  = *(const float4*)&sB[k][tn*4];
            u64 A01 = pk2(a01.x, a01.y);
            u64 A23 = pk2(a23.x, a23.y);
            u64 B0 = pk2(bq.x, bq.x), B1 = pk2(bq.y, bq.y);
            u64 B2 = pk2(bq.z, bq.z), B3 = pk2(bq.w, bq.w);
            acc2[0][0] = fma2(A01, B0, acc2[0][0]);
            acc2[0][1] = fma2(A01, B1, acc2[0][1]);
            acc2[0][2] = fma2(A01, B2, acc2[0][2]);
            acc2[0][3] = fma2(A01, B3, acc2[0][3]);
            acc2[1][0] = fma2(A23, B0, acc2[1][0]);
            acc2[1][1] = fma2(A23, B1, acc2[1][1]);
            acc2[1][2] = fma2(A23, B2, acc2[1][2]);
            acc2[1][3] = fma2(A23, B3, acc2[1][3]);
        }
    }
    float4 bias4 = *(const float4*)(bias + nb + tn*4);
    u64 S2 = pk2(SCALE2, SCALE2);
    u64 BS[4] = { pk2(bias4.x*SCALE2, bias4.x*SCALE2), pk2(bias4.y*SCALE2, bias4.y*SCALE2),
                  pk2(bias4.z*SCALE2, bias4.z*SCALE2), pk2(bias4.w*SCALE2, bias4.w*SCALE2) };
    #pragma unroll
    for (int ip = 0; ip < 2; ip++) {
        float lo[4], hi[4];
        #pragma unroll
        for (int j = 0; j < 4; j++) {
            u64 r = fma2(acc2[ip][j], S2, BS[j]);
            upk2(r, lo[j], hi[j]);
        }
        *(float4*)(P + (mb + tm*4 + ip*2 + 0) * D_ + nb + tn*4) = make_float4(lo[0], lo[1], lo[2], lo[3]);
        *(float4*)(P + (mb + tm*4 + ip*2 + 1) * D_ + nb + tn*4) = make_float4(hi[0], hi[1], hi[2], hi[3]);
    }
}

// ---------------------------------------------------------------------------
// K2: score[b][qi][jj] = D - 2 * sum_d 1/(1+2^{q'[qi][d]+v'[jj][d]})
// Quad-rational: one division per float4 of d; both jj quads ride the two
// lanes of f32x2 ops; all divisions via FMA-pipe Newton. MUFU carries exactly
// one EX2 per element (the floor).
// ---------------------------------------------------------------------------
__global__ __launch_bounds__(256) void score_kernel()
{
    constexpr int DK = 32;
    __shared__ float4 sQ[64 * 8];   // pos = r*8 + (vec ^ (r&7))
    __shared__ float4 sV[32 * 8];

    const int tid = threadIdx.x;
    const int b   = blockIdx.y;
    const int qt  = blockIdx.x >> 4;     // 0..3  (TQ/64)
    const int jt  = blockIdx.x & 15;     // 0..15 (TV/32)
    const int qbase = qt * 64, jbase = jt * 32;
    const float* qp = g_qproj + (b * TQ + qbase) * D_;
    const float* vp = g_vproj + (b * TV + jbase) * D_;
    const int tq = tid >> 4, tj = tid & 15;

    const u64 ONE2 = pk2(1.0f, 1.0f);
    const u64 TWO2 = pk2(2.0f, 2.0f);
    const u64 NEG1 = pk2(-1.0f, -1.0f);

    u64 acc2[4] = {};   // acc2[a] = (sum for jj0, sum for jj1)

    for (int dc = 0; dc < D_; dc += DK) {
        __syncthreads();
        #pragma unroll
        for (int i = 0; i < 2; i++) {          // 64 rows x 8 vecs of Q
            int idx = i * 256 + tid;
            int r = idx >> 3, vec = idx & 7;
            sQ[r*8 + (vec ^ (r & 7))] = *(const float4*)(qp + r * D_ + dc + vec * 4);
        }
        {                                       // 32 rows x 8 vecs of V
            int r = tid >> 3, vec = tid & 7;
            sV[r*8 + (vec ^ (r & 7))] = *(const float4*)(vp + r * D_ + dc + vec * 4);
        }
        __syncthreads();

        #pragma unroll
        for (int vec = 0; vec < 8; vec++) {
            float4 qv[4], vv[2];
            #pragma unroll
            for (int a = 0; a < 4; a++) { int r = a*16 + tq; qv[a] = sQ[r*8 + (vec ^ (r & 7))]; }
            #pragma unroll
            for (int bb = 0; bb < 2; bb++) { int r = bb*16 + tj; vv[bb] = sV[r*8 + (vec ^ (r & 7))]; }

            #pragma unroll
            for (int a = 0; a < 4; a++) {
                float4 q = qv[a];
                // scalar args + EX2 (MUFU), then everything packed (lane = jj)
                float e0a = fast_ex2(q.x + vv[0].x), e0b = fast_ex2(q.x + vv[1].x);
                float e1a = fast_ex2(q.y + vv[0].y), e1b = fast_ex2(q.y + vv[1].y);
                float e2a = fast_ex2(q.z + vv[0].z), e2b = fast_ex2(q.z + vv[1].z);
                float e3a = fast_ex2(q.w + vv[0].w), e3b = fast_ex2(q.w + vv[1].w);
                u64 z0 = add2(pk2(e0a, e0b), ONE2);
                u64 z1 = add2(pk2(e1a, e1b), ONE2);
                u64 z2 = add2(pk2(e2a, e2b), ONE2);
                u64 z3 = add2(pk2(e3a, e3b), ONE2);
                u64 p12  = mul2(z0, z1);
                u64 p34  = mul2(z2, z3);
                u64 zs01 = add2(z0, z1);
                u64 zs23 = add2(z2, z3);
                u64 num  = fma2(p12, zs23, mul2(p34, zs01));
                u64 den  = mul2(p12, p34);
                // packed Newton reciprocal (FMA pipe; seeds on ALU pipe)
                float d0, d1; upk2(den, d0, d1);
                u64 y = pk2(__uint_as_float(0x7EF311C3u - __float_as_uint(d0)),
                            __uint_as_float(0x7EF311C3u - __float_as_uint(d1)));
                u64 nd = mul2(den, NEG1);
                y = mul2(y, fma2(nd, y, TWO2));
                y = mul2(y, fma2(nd, y, TWO2));
                acc2[a] = fma2(num, y, acc2[a]);
            }
        }
    }

    #pragma unroll
    for (int a = 0; a < 4; a++) {
        float s0, s1; upk2(acc2[a], s0, s1);
        int qi = qbase + a*16 + tq;
        g_score[(b * TQ + qi) * TV + jbase + tj]      = (float)D_ - 2.0f * s0;
        g_score[(b * TQ + qi) * TV + jbase + 16 + tj] = (float)D_ - 2.0f * s1;
    }
}

// ---------------------------------------------------------------------------
// K3: softmax over TV=512. Slab of 16 rows per block (one warp per 2 rows),
// in-place alignment into g_score (coalesced) + transposed alignment_t via
// smem tile (coalesced STG).
// ---------------------------------------------------------------------------
__global__ __launch_bounds__(256) void softmax_kernel(float* __restrict__ out_at)
{
    __shared__ float sm[16][513];
    const int b    = blockIdx.x >> 4;     // 128 blocks = 8 b x 16 slabs
    const int slab = blockIdx.x & 15;
    const int q0   = slab * 16;
    const int wid  = threadIdx.x >> 5, lane = threadIdx.x & 31;

    #pragma unroll
    for (int rr = 0; rr < 2; rr++) {
        const int r = wid * 2 + rr;
        float* s = g_score + (size_t)(b * TQ + q0 + r) * TV;
        float4 v[4];
        #pragma unroll
        for (int k = 0; k < 4; k++) v[k] = *(const float4*)(s + (k*32 + lane)*4);
        float m = -1e30f;
        #pragma unroll
        for (int k = 0; k < 4; k++)
            m = fmaxf(m, fmaxf(fmaxf(v[k].x, v[k].y), fmaxf(v[k].z, v[k].w)));
        #pragma unroll
        for (int o = 16; o; o >>= 1) m = fmaxf(m, __shfl_xor_sync(0xffffffffu, m, o));

        float4 e[4]; float sum = 0.0f;
        #pragma unroll
        for (int k = 0; k < 4; k++) {
            e[k].x = fast_ex2((v[k].x - m) * LOG2E);
            e[k].y = fast_ex2((v[k].y - m) * LOG2E);
            e[k].z = fast_ex2((v[k].z - m) * LOG2E);
            e[k].w = fast_ex2((v[k].w - m) * LOG2E);
            sum += (e[k].x + e[k].y) + (e[k].z + e[k].w);
        }
        #pragma unroll
        for (int o = 16; o; o >>= 1) sum += __shfl_xor_sync(0xffffffffu, sum, o);
        float inv = 1.0f / sum;

        #pragma unroll
        for (int k = 0; k < 4; k++) {
            float4 a = make_float4(e[k].x*inv, e[k].y*inv, e[k].z*inv, e[k].w*inv);
            *(float4*)(s + (k*32 + lane)*4) = a;
            int col = (k*32 + lane)*4;
            sm[r][col+0] = a.x; sm[r][col+1] = a.y; sm[r][col+2] = a.z; sm[r][col+3] = a.w;
        }
    }
    __syncthreads();

    // transposed write: out_at[(b*TV + j)*TQ + q0 + i] = sm[i][j]
    const int i = lane & 15;
    const int jb = wid * 64 + (lane >> 4) * 32;
    float* dst = out_at + (size_t)(b * TV) * TQ + q0 + i;
    #pragma unroll
    for (int jj = 0; jj < 32; jj++) {
        int j = jb + jj;
        dst[(size_t)j * TQ] = sm[i][j];
    }
}

// ---------------------------------------------------------------------------
// K4: context[b] = alignment[b] (256x512) @ value[b] (512x256), f32x2 inner.
// ---------------------------------------------------------------------------
__global__ __launch_bounds__(256) void context_kernel(
    const float* __restrict__ value, float* __restrict__ out)
{
    __shared__ float sAT[16][64];
    __shared__ float sB[16][64];
    const int tid = threadIdx.x;
    const int b  = blockIdx.z;
    const int mb = blockIdx.y * 64;
    const int nb = blockIdx.x * 64;
    const float* A = g_score + b * TQ * TV;      // alignment
    const float* V = value + b * TV * D_;
    float* C = out + b * TQ * (2 * D_);
    const int tm = tid >> 4, tn = tid & 15;
    const int arow = tid >> 2, akv = tid & 3;
    const int brow = tid >> 4, bcv = tid & 15;

    u64 acc2[2][4] = {};

    for (int kt = 0; kt < TV; kt += 16) {
        float4 av = *(const float4*)(A + (mb + arow) * TV + kt + akv * 4);
        float4 bv = *(const float4*)(V + (kt + brow) * D_ + nb + bcv * 4);
        __syncthreads();
        sAT[akv*4+0][arow] = av.x; sAT[akv*4+1][arow] = av.y;
        sAT[akv*4+2][arow] = av.z; sAT[akv*4+3][arow] = av.w;
        *(float4*)&sB[brow][bcv*4] = bv;
        __syncthreads();
        #pragma unroll
        for (int k = 0; k < 16; k++) {
            float2 a01 = *(const float2*)&sAT[k][tm*4];
            float2 a23 = *(const float2*)&sAT[k][tm*4 + 2];
            float4 bq  = *(const float4*)&sB[k][tn*4];
            u64 A01 = pk2(a01.x, a01.y);
            u64 A23 = pk2(a23.x, a23.y);
            u64 B0 = pk2(bq.x, bq.x), B1 = pk2(bq.y, bq.y);
            u64 B2 = pk2(bq.z, bq.z), B3 = pk2(bq.w, bq.w);
            acc2[0][0] = fma2(A01, B0, acc2[0][0]);
            acc2[0][1] = fma2(A01, B1, acc2[0][1]);
            acc2[0][2] = fma2(A01, B2, acc2[0][2]);
            acc2[0][3] = fma2(A01, B3, acc2[0][3]);
            acc2[1][0] = fma2(A23, B0, acc2[1][0]);
            acc2[1][1] = fma2(A23, B1, acc2[1][1]);
            acc2[1][2] = fma2(A23, B2, acc2[1][2]);
            acc2[1][3] = fma2(A23, B3, acc2[1][3]);
        }
    }
    #pragma unroll
    for (int ip = 0; ip < 2; ip++) {
        float lo[4], hi[4];
        #pragma unroll
        for (int j = 0; j < 4; j++) upk2(acc2[ip][j], lo[j], hi[j]);
        *(float4*)(C + (mb + tm*4 + ip*2 + 0) * (2 * D_) + nb + tn*4) = make_float4(lo[0], lo[1], lo[2], lo[3]);
        *(float4*)(C + (mb + tm*4 + ip*2 + 1) * (2 * D_) + nb + tn*4) = make_float4(hi[0], hi[1], hi[2], hi[3]);
    }
}

// ---------------------------------------------------------------------------
// K5: out[b][qi][D:2D] = query[b][qi][:]
// ---------------------------------------------------------------------------
__global__ __launch_bounds__(256) void copy_query_kernel(
    const float* __restrict__ query, float* __restrict__ out)
{
    int g = blockIdx.x * 256 + threadIdx.x;      // over B*TQ*D/4 float4s
    int row = g >> 6, vec = g & 63;              // 64 float4s per row
    ((float4*)out)[row * 128 + 64 + vec] = ((const float4*)query)[g];
}

// ---------------------------------------------------------------------------
extern "C" void kernel_launch(void* const* d_in, const int* in_sizes, int n_in,
                              void* d_out, int out_size)
{
    const float* query = (const float*)d_in[0];   // [8,256,256]
    const float* value = (const float*)d_in[1];   // [8,512,256]
    const float* W1    = (const float*)d_in[2];   // [256,256]
    const float* b1    = (const float*)d_in[3];   // [256]
    const float* W2    = (const float*)d_in[4];   // [256,256]
    const float* b2    = (const float*)d_in[5];   // [256]
    float* out = (float*)d_out;                   // [8*256*512 ctx] + [8*512*256 align_t]

    void *qp_, *vp_;
    cudaGetSymbolAddress(&qp_, g_qproj);
    cudaGetSymbolAddress(&vp_, g_vproj);

    proj_kernel<<<dim3(4, 32), 256>>>(query, W1, b1, (float*)qp_);   // 2048x256
    proj_kernel<<<dim3(4, 64), 256>>>(value, W2, b2, (float*)vp_);   // 4096x256
    score_kernel<<<dim3(64, 8), 256>>>();
    softmax_kernel<<<128, 256>>>(out + B_ * TQ * 2 * D_);
    context_kernel<<<dim3(4, 4, 8), 256>>>(value, out);
    copy_query_kernel<<<512, 256>>>(query, out);
}

// round 4
// speedup vs baseline: 1.3438x; 1.0397x over previous
#include <cuda_runtime.h>

#define DEV_INLINE __device__ __forceinline__
using u64 = unsigned long long;

constexpr int B_  = 8;
constexpr int TQ  = 256;
constexpr int TV  = 512;
constexpr int D_  = 256;
constexpr float SCALE2 = 2.8853900817779268f;   // 2*log2(e): e^{2x} = 2^{SCALE2*x}
constexpr float LOG2E  = 1.4426950408889634f;

// Scratch (device globals — no allocation allowed)
__device__ float g_qproj[B_ * TQ * D_];   // (query@W1 + b1) * SCALE2
__device__ float g_vproj[B_ * TV * D_];   // (value@W2 + b2) * SCALE2
__device__ float g_score[B_ * TQ * TV];   // scores, then alignment in-place

DEV_INLINE float fast_ex2(float x) { float y; asm("ex2.approx.f32 %0, %1;" : "=f"(y) : "f"(x)); return y; }

// ---- packed f32x2 helpers ----
DEV_INLINE u64 pk2(float lo, float hi) { u64 r; asm("mov.b64 %0, {%1, %2};" : "=l"(r) : "f"(lo), "f"(hi)); return r; }
DEV_INLINE void upk2(u64 p, float& lo, float& hi) { asm("mov.b64 {%0, %1}, %2;" : "=f"(lo), "=f"(hi) : "l"(p)); }
DEV_INLINE u64 bc2(float x) { u64 r; asm("mov.b64 %0, {%1, %1};" : "=l"(r) : "f"(x)); return r; }
DEV_INLINE u64 add2(u64 a, u64 b) { u64 r; asm("add.rn.f32x2 %0, %1, %2;" : "=l"(r) : "l"(a), "l"(b)); return r; }
DEV_INLINE u64 mul2(u64 a, u64 b) { u64 r; asm("mul.rn.f32x2 %0, %1, %2;" : "=l"(r) : "l"(a), "l"(b)); return r; }
DEV_INLINE u64 fma2(u64 a, u64 b, u64 c) { u64 r; asm("fma.rn.f32x2 %0, %1, %2, %3;" : "=l"(r) : "l"(a), "l"(b), "l"(c)); return r; }

// Two EX2s computed directly into a register pair (splitter/joiner movs are
// RA-coalescible since inputs/outputs live in pairs on both sides).
DEV_INLINE u64 ex2_pair(u64 a) {
    u64 r;
    asm("{\n\t.reg .f32 al, ah, rl, rh;\n\t"
        "mov.b64 {al, ah}, %1;\n\t"
        "ex2.approx.f32 rl, al;\n\t"
        "ex2.approx.f32 rh, ah;\n\t"
        "mov.b64 %0, {rl, rh};\n\t}"
        : "=l"(r) : "l"(a));
    return r;
}

// Packed Newton reciprocal: magic seed (ALU) + 2 iterations (FMA pipe).
DEV_INLINE u64 nrcp2(u64 den, u64 TWO2, u64 NEG1) {
    float d0, d1; upk2(den, d0, d1);
    u64 y = pk2(__uint_as_float(0x7EF311C3u - __float_as_uint(d0)),
                __uint_as_float(0x7EF311C3u - __float_as_uint(d1)));
    u64 nd = mul2(den, NEG1);
    y = mul2(y, fma2(nd, y, TWO2));
    y = mul2(y, fma2(nd, y, TWO2));
    return y;
}

// ---------------------------------------------------------------------------
// K1: projection GEMM  P[m][e] = (sum_d X[m][d]*W[d][e] + b[e]) * SCALE2
// ---------------------------------------------------------------------------
__global__ __launch_bounds__(256) void proj_kernel(
    const float* __restrict__ X, const float* __restrict__ W,
    const float* __restrict__ bias, float* __restrict__ P)
{
    __shared__ float sAT[16][64];
    __shared__ float sB[16][64];
    const int tid = threadIdx.x;
    const int mb = blockIdx.y * 64;
    const int nb = blockIdx.x * 64;
    const int tm = tid >> 4, tn = tid & 15;
    const int arow = tid >> 2, akv = tid & 3;
    const int brow = tid >> 4, bcv = tid & 15;

    u64 acc2[2][4] = {};

    for (int kt = 0; kt < D_; kt += 16) {
        float4 av = *(const float4*)(X + (mb + arow) * D_ + kt + akv * 4);
        float4 bv = *(const float4*)(W + (kt + brow) * D_ + nb + bcv * 4);
        __syncthreads();
        sAT[akv*4+0][arow] = av.x; sAT[akv*4+1][arow] = av.y;
        sAT[akv*4+2][arow] = av.z; sAT[akv*4+3][arow] = av.w;
        *(float4*)&sB[brow][bcv*4] = bv;
        __syncthreads();
        #pragma unroll
        for (int k = 0; k < 16; k++) {
            float2 a01 = *(const float2*)&sAT[k][tm*4];
            float2 a23 = *(const float2*)&sAT[k][tm*4 + 2];
            float4 bq  = *(const float4*)&sB[k][tn*4];
            u64 A01 = pk2(a01.x, a01.y);
            u64 A23 = pk2(a23.x, a23.y);
            u64 B0 = bc2(bq.x), B1 = bc2(bq.y), B2 = bc2(bq.z), B3 = bc2(bq.w);
            acc2[0][0] = fma2(A01, B0, acc2[0][0]);
            acc2[0][1] = fma2(A01, B1, acc2[0][1]);
            acc2[0][2] = fma2(A01, B2, acc2[0][2]);
            acc2[0][3] = fma2(A01, B3, acc2[0][3]);
            acc2[1][0] = fma2(A23, B0, acc2[1][0]);
            acc2[1][1] = fma2(A23, B1, acc2[1][1]);
            acc2[1][2] = fma2(A23, B2, acc2[1][2]);
            acc2[1][3] = fma2(A23, B3, acc2[1][3]);
        }
    }
    float4 bias4 = *(const float4*)(bias + nb + tn*4);
    u64 S2 = pk2(SCALE2, SCALE2);
    u64 BS[4] = { bc2(bias4.x*SCALE2), bc2(bias4.y*SCALE2),
                  bc2(bias4.z*SCALE2), bc2(bias4.w*SCALE2) };
    #pragma unroll
    for (int ip = 0; ip < 2; ip++) {
        float lo[4], hi[4];
        #pragma unroll
        for (int j = 0; j < 4; j++) {
            u64 r = fma2(acc2[ip][j], S2, BS[j]);
            upk2(r, lo[j], hi[j]);
        }
        *(float4*)(P + (mb + tm*4 + ip*2 + 0) * D_ + nb + tn*4) = make_float4(lo[0], lo[1], lo[2], lo[3]);
        *(float4*)(P + (mb + tm*4 + ip*2 + 1) * D_ + nb + tn*4) = make_float4(hi[0], hi[1], hi[2], hi[3]);
    }
}

// ---------------------------------------------------------------------------
// K2: score = D - 2*sum_d sigmoid-quads. V tile stored jj-PAIRED in smem so
// the two jj lanes of every f32x2 op load as native u64 pairs (no packing).
// All divisions = packed Newton (FMA pipe). MUFU carries exactly 1 EX2/elem.
// ---------------------------------------------------------------------------
__global__ __launch_bounds__(256) void score_kernel()
{
    constexpr int DK = 32;
    __shared__ float4 sQ[64 * 8];        // swizzled: r*8 + (vec ^ (r&7))
    __shared__ float  sVP[16 * 16 * 4];  // [dp][tj][4]: {lo(d0),hi(d0),lo(d1),hi(d1)}

    const int tid = threadIdx.x;
    const int b   = blockIdx.y;
    const int qt  = blockIdx.x >> 4;     // 0..3  (TQ/64)
    const int jt  = blockIdx.x & 15;     // 0..15 (TV/32)
    const int qbase = qt * 64, jbase = jt * 32;
    const float* qp = g_qproj + (b * TQ + qbase) * D_;
    const float* vp = g_vproj + (b * TV + jbase) * D_;
    const int tq = tid >> 4, tj = tid & 15;

    const u64 ONE2 = pk2(1.0f, 1.0f);
    const u64 TWO2 = pk2(2.0f, 2.0f);
    const u64 NEG1 = pk2(-1.0f, -1.0f);

    u64 acc2[4] = {};   // lanes = (jj=jbase+tj, jj=jbase+16+tj)

    for (int dc = 0; dc < D_; dc += DK) {
        __syncthreads();
        #pragma unroll
        for (int i = 0; i < 2; i++) {          // Q: 64 rows x 8 vecs
            int idx = i * 256 + tid;
            int r = idx >> 3, vec = idx & 7;
            sQ[r*8 + (vec ^ (r & 7))] = *(const float4*)(qp + r * D_ + dc + vec * 4);
        }
        {                                       // V: 32 rows x 8 vecs, paired layout
            int r = tid >> 3, vec = tid & 7;
            float4 v = *(const float4*)(vp + r * D_ + dc + vec * 4);
            int half = r >> 4, row = r & 15;
            float* base0 = &sVP[((2*vec)   * 16 + row) * 4];
            float* base1 = &sVP[((2*vec+1) * 16 + row) * 4];
            base0[half]     = v.x;  base0[2 + half] = v.y;
            base1[half]     = v.z;  base1[2 + half] = v.w;
        }
        __syncthreads();

        #pragma unroll
        for (int vec = 0; vec < 8; vec++) {
            ulonglong2 vp01 = *(const ulonglong2*)&sVP[((2*vec)   * 16 + tj) * 4];
            ulonglong2 vp23 = *(const ulonglong2*)&sVP[((2*vec+1) * 16 + tj) * 4];
            float4 qv[4];
            #pragma unroll
            for (int a = 0; a < 4; a++) { int r = a*16 + tq; qv[a] = sQ[r*8 + (vec ^ (r & 7))]; }

            #pragma unroll
            for (int a = 0; a < 4; a++) {
                float4 q = qv[a];
                u64 e0 = ex2_pair(add2(bc2(q.x), vp01.x));
                u64 e1 = ex2_pair(add2(bc2(q.y), vp01.y));
                u64 e2 = ex2_pair(add2(bc2(q.z), vp23.x));
                u64 e3 = ex2_pair(add2(bc2(q.w), vp23.y));
                u64 z0 = add2(e0, ONE2);
                u64 z1 = add2(e1, ONE2);
                u64 z2 = add2(e2, ONE2);
                u64 z3 = add2(e3, ONE2);
                u64 p12  = mul2(z0, z1);
                u64 p34  = mul2(z2, z3);
                u64 zs01 = add2(z0, z1);
                u64 zs23 = add2(z2, z3);
                u64 num  = fma2(p12, zs23, mul2(p34, zs01));
                u64 den  = mul2(p12, p34);
                u64 y    = nrcp2(den, TWO2, NEG1);
                acc2[a]  = fma2(num, y, acc2[a]);
            }
        }
    }

    #pragma unroll
    for (int a = 0; a < 4; a++) {
        float s0, s1; upk2(acc2[a], s0, s1);
        int qi = qbase + a*16 + tq;
        g_score[(b * TQ + qi) * TV + jbase + tj]      = (float)D_ - 2.0f * s0;
        g_score[(b * TQ + qi) * TV + jbase + 16 + tj] = (float)D_ - 2.0f * s1;
    }
}

// ---------------------------------------------------------------------------
// K3: softmax over TV=512 (16-row slab, warp per 2 rows) + transposed output.
// ---------------------------------------------------------------------------
__global__ __launch_bounds__(256) void softmax_kernel(float* __restrict__ out_at)
{
    __shared__ float sm[16][513];
    const int b    = blockIdx.x >> 4;
    const int slab = blockIdx.x & 15;
    const int q0   = slab * 16;
    const int wid  = threadIdx.x >> 5, lane = threadIdx.x & 31;

    #pragma unroll
    for (int rr = 0; rr < 2; rr++) {
        const int r = wid * 2 + rr;
        float* s = g_score + (size_t)(b * TQ + q0 + r) * TV;
        float4 v[4];
        #pragma unroll
        for (int k = 0; k < 4; k++) v[k] = *(const float4*)(s + (k*32 + lane)*4);
        float m = -1e30f;
        #pragma unroll
        for (int k = 0; k < 4; k++)
            m = fmaxf(m, fmaxf(fmaxf(v[k].x, v[k].y), fmaxf(v[k].z, v[k].w)));
        #pragma unroll
        for (int o = 16; o; o >>= 1) m = fmaxf(m, __shfl_xor_sync(0xffffffffu, m, o));

        float4 e[4]; float sum = 0.0f;
        #pragma unroll
        for (int k = 0; k < 4; k++) {
            e[k].x = fast_ex2((v[k].x - m) * LOG2E);
            e[k].y = fast_ex2((v[k].y - m) * LOG2E);
            e[k].z = fast_ex2((v[k].z - m) * LOG2E);
            e[k].w = fast_ex2((v[k].w - m) * LOG2E);
            sum += (e[k].x + e[k].y) + (e[k].z + e[k].w);
        }
        #pragma unroll
        for (int o = 16; o; o >>= 1) sum += __shfl_xor_sync(0xffffffffu, sum, o);
        float inv = 1.0f / sum;

        #pragma unroll
        for (int k = 0; k < 4; k++) {
            float4 a = make_float4(e[k].x*inv, e[k].y*inv, e[k].z*inv, e[k].w*inv);
            *(float4*)(s + (k*32 + lane)*4) = a;
            int col = (k*32 + lane)*4;
            sm[r][col+0] = a.x; sm[r][col+1] = a.y; sm[r][col+2] = a.z; sm[r][col+3] = a.w;
        }
    }
    __syncthreads();

    const int i = lane & 15;
    const int jb = wid * 64 + (lane >> 4) * 32;
    float* dst = out_at + (size_t)(b * TV) * TQ + q0 + i;
    #pragma unroll
    for (int jj = 0; jj < 32; jj++) {
        int j = jb + jj;
        dst[(size_t)j * TQ] = sm[i][j];
    }
}

// ---------------------------------------------------------------------------
// K4: context[b] = alignment[b] (256x512) @ value[b] (512x256), f32x2 inner.
// ---------------------------------------------------------------------------
__global__ __launch_bounds__(256) void context_kernel(
    const float* __restrict__ value, float* __restrict__ out)
{
    __shared__ float sAT[16][64];
    __shared__ float sB[16][64];
    const int tid = threadIdx.x;
    const int b  = blockIdx.z;
    const int mb = blockIdx.y * 64;
    const int nb = blockIdx.x * 64;
    const float* A = g_score + b * TQ * TV;
    const float* V = value + b * TV * D_;
    float* C = out + b * TQ * (2 * D_);
    const int tm = tid >> 4, tn = tid & 15;
    const int arow = tid >> 2, akv = tid & 3;
    const int brow = tid >> 4, bcv = tid & 15;

    u64 acc2[2][4] = {};

    for (int kt = 0; kt < TV; kt += 16) {
        float4 av = *(const float4*)(A + (mb + arow) * TV + kt + akv * 4);
        float4 bv = *(const float4*)(V + (kt + brow) * D_ + nb + bcv * 4);
        __syncthreads();
        sAT[akv*4+0][arow] = av.x; sAT[akv*4+1][arow] = av.y;
        sAT[akv*4+2][arow] = av.z; sAT[akv*4+3][arow] = av.w;
        *(float4*)&sB[brow][bcv*4] = bv;
        __syncthreads();
        #pragma unroll
        for (int k = 0; k < 16; k++) {
            float2 a01 = *(const float2*)&sAT[k][tm*4];
            float2 a23 = *(const float2*)&sAT[k][tm*4 + 2];
            float4 bq  = *(const float4*)&sB[k][tn*4];
            u64 A01 = pk2(a01.x, a01.y);
            u64 A23 = pk2(a23.x, a23.y);
            u64 B0 = bc2(bq.x), B1 = bc2(bq.y), B2 = bc2(bq.z), B3 = bc2(bq.w);
            acc2[0][0] = fma2(A01, B0, acc2[0][0]);
            acc2[0][1] = fma2(A01, B1, acc2[0][1]);
            acc2[0][2] = fma2(A01, B2, acc2[0][2]);
            acc2[0][3] = fma2(A01, B3, acc2[0][3]);
            acc2[1][0] = fma2(A23, B0, acc2[1][0]);
            acc2[1][1] = fma2(A23, B1, acc2[1][1]);
            acc2[1][2] = fma2(A23, B2, acc2[1][2]);
            acc2[1][3] = fma2(A23, B3, acc2[1][3]);
        }
    }
    #pragma unroll
    for (int ip = 0; ip < 2; ip++) {
        float lo[4], hi[4];
        #pragma unroll
        for (int j = 0; j < 4; j++) upk2(acc2[ip][j], lo[j], hi[j]);
        *(float4*)(C + (mb + tm*4 + ip*2 + 0) * (2 * D_) + nb + tn*4) = make_float4(lo[0], lo[1], lo[2], lo[3]);
        *(float4*)(C + (mb + tm*4 + ip*2 + 1) * (2 * D_) + nb + tn*4) = make_float4(hi[0], hi[1], hi[2], hi[3]);
    }
}

// ---------------------------------------------------------------------------
// K5: out[b][qi][D:2D] = query[b][qi][:]
// ---------------------------------------------------------------------------
__global__ __launch_bounds__(256) void copy_query_kernel(
    const float* __restrict__ query, float* __restrict__ out)
{
    int g = blockIdx.x * 256 + threadIdx.x;
    int row = g >> 6, vec = g & 63;
    ((float4*)out)[row * 128 + 64 + vec] = ((const float4*)query)[g];
}

// ---------------------------------------------------------------------------
extern "C" void kernel_launch(void* const* d_in, const int* in_sizes, int n_in,
                              void* d_out, int out_size)
{
    const float* query = (const float*)d_in[0];   // [8,256,256]
    const float* value = (const float*)d_in[1];   // [8,512,256]
    const float* W1    = (const float*)d_in[2];   // [256,256]
    const float* b1    = (const float*)d_in[3];   // [256]
    const float* W2    = (const float*)d_in[4];   // [256,256]
    const float* b2    = (const float*)d_in[5];   // [256]
    float* out = (float*)d_out;

    void *qp_, *vp_;
    cudaGetSymbolAddress(&qp_, g_qproj);
    cudaGetSymbolAddress(&vp_, g_vproj);

    proj_kernel<<<dim3(4, 32), 256>>>(query, W1, b1, (float*)qp_);
    proj_kernel<<<dim3(4, 64), 256>>>(value, W2, b2, (float*)vp_);
    score_kernel<<<dim3(64, 8), 256>>>();
    softmax_kernel<<<128, 256>>>(out + B_ * TQ * 2 * D_);
    context_kernel<<<dim3(4, 4, 8), 256>>>(value, out);
    copy_query_kernel<<<512, 256>>>(query, out);
}

// round 5
// speedup vs baseline: 1.7349x; 1.2911x over previous
#include <cuda_runtime.h>

#define DEV_INLINE __device__ __forceinline__
using u64 = unsigned long long;

constexpr int B_  = 8;
constexpr int TQ  = 256;
constexpr int TV  = 512;
constexpr int D_  = 256;
constexpr float SCALE2 = 2.8853900817779268f;   // 2*log2(e): e^{2x} = 2^{SCALE2*x}
constexpr float LOG2E  = 1.4426950408889634f;

// Scratch (device globals — no allocation allowed)
__device__ float g_qproj[B_ * TQ * D_];   // EQ  = 2^{SCALE2*(q@W1+b1)}
__device__ float g_vproj[B_ * TV * D_];   // EV' = 2^{SCALE2*(v@W2+b2) - 16}
__device__ float g_score[B_ * TQ * TV];   // scores, then alignment in-place

DEV_INLINE float fast_ex2(float x) { float y; asm("ex2.approx.f32 %0, %1;" : "=f"(y) : "f"(x)); return y; }

// ---- packed f32x2 helpers ----
DEV_INLINE u64 pk2(float lo, float hi) { u64 r; asm("mov.b64 %0, {%1, %2};" : "=l"(r) : "f"(lo), "f"(hi)); return r; }
DEV_INLINE void upk2(u64 p, float& lo, float& hi) { asm("mov.b64 {%0, %1}, %2;" : "=f"(lo), "=f"(hi) : "l"(p)); }
DEV_INLINE u64 bc2(float x) { u64 r; asm("mov.b64 %0, {%1, %1};" : "=l"(r) : "f"(x)); return r; }
DEV_INLINE u64 add2(u64 a, u64 b) { u64 r; asm("add.rn.f32x2 %0, %1, %2;" : "=l"(r) : "l"(a), "l"(b)); return r; }
DEV_INLINE u64 mul2(u64 a, u64 b) { u64 r; asm("mul.rn.f32x2 %0, %1, %2;" : "=l"(r) : "l"(a), "l"(b)); return r; }
DEV_INLINE u64 fma2(u64 a, u64 b, u64 c) { u64 r; asm("fma.rn.f32x2 %0, %1, %2, %3;" : "=l"(r) : "l"(a), "l"(b), "l"(c)); return r; }

// Two rcp.approx computed on a register pair (MUFU pipe, ~1 ulp).
DEV_INLINE u64 rcp2_pair(u64 a) {
    u64 r;
    asm("{\n\t.reg .f32 al, ah, rl, rh;\n\t"
        "mov.b64 {al, ah}, %1;\n\t"
        "rcp.approx.f32 rl, al;\n\t"
        "rcp.approx.f32 rh, ah;\n\t"
        "mov.b64 %0, {rl, rh};\n\t}"
        : "=l"(r) : "l"(a));
    return r;
}

// ---------------------------------------------------------------------------
// K1: projection GEMM + exponential epilogue:
//     P[m][e] = 2^{ SCALE2*(sum_d X[m][d]*W[d][e] + b[e]) + shift }
// shift = 0 for Q, -16 for V (folds the range prescale into the table).
// ---------------------------------------------------------------------------
__global__ __launch_bounds__(256) void proj_kernel(
    const float* __restrict__ X, const float* __restrict__ W,
    const float* __restrict__ bias, float* __restrict__ P, float shift)
{
    __shared__ float sAT[16][64];
    __shared__ float sB[16][64];
    const int tid = threadIdx.x;
    const int mb = blockIdx.y * 64;
    const int nb = blockIdx.x * 64;
    const int tm = tid >> 4, tn = tid & 15;
    const int arow = tid >> 2, akv = tid & 3;
    const int brow = tid >> 4, bcv = tid & 15;

    u64 acc2[2][4] = {};

    for (int kt = 0; kt < D_; kt += 16) {
        float4 av = *(const float4*)(X + (mb + arow) * D_ + kt + akv * 4);
        float4 bv = *(const float4*)(W + (kt + brow) * D_ + nb + bcv * 4);
        __syncthreads();
        sAT[akv*4+0][arow] = av.x; sAT[akv*4+1][arow] = av.y;
        sAT[akv*4+2][arow] = av.z; sAT[akv*4+3][arow] = av.w;
        *(float4*)&sB[brow][bcv*4] = bv;
        __syncthreads();
        #pragma unroll
        for (int k = 0; k < 16; k++) {
            float2 a01 = *(const float2*)&sAT[k][tm*4];
            float2 a23 = *(const float2*)&sAT[k][tm*4 + 2];
            float4 bq  = *(const float4*)&sB[k][tn*4];
            u64 A01 = pk2(a01.x, a01.y);
            u64 A23 = pk2(a23.x, a23.y);
            u64 B0 = bc2(bq.x), B1 = bc2(bq.y), B2 = bc2(bq.z), B3 = bc2(bq.w);
            acc2[0][0] = fma2(A01, B0, acc2[0][0]);
            acc2[0][1] = fma2(A01, B1, acc2[0][1]);
            acc2[0][2] = fma2(A01, B2, acc2[0][2]);
            acc2[0][3] = fma2(A01, B3, acc2[0][3]);
            acc2[1][0] = fma2(A23, B0, acc2[1][0]);
            acc2[1][1] = fma2(A23, B1, acc2[1][1]);
            acc2[1][2] = fma2(A23, B2, acc2[1][2]);
            acc2[1][3] = fma2(A23, B3, acc2[1][3]);
        }
    }
    float4 bias4 = *(const float4*)(bias + nb + tn*4);
    u64 S2 = pk2(SCALE2, SCALE2);
    u64 BS[4] = { bc2(bias4.x*SCALE2 + shift), bc2(bias4.y*SCALE2 + shift),
                  bc2(bias4.z*SCALE2 + shift), bc2(bias4.w*SCALE2 + shift) };
    #pragma unroll
    for (int ip = 0; ip < 2; ip++) {
        float lo[4], hi[4];
        #pragma unroll
        for (int j = 0; j < 4; j++) {
            u64 r = fma2(acc2[ip][j], S2, BS[j]);
            upk2(r, lo[j], hi[j]);
            lo[j] = fast_ex2(lo[j]);
            hi[j] = fast_ex2(hi[j]);
        }
        *(float4*)(P + (mb + tm*4 + ip*2 + 0) * D_ + nb + tn*4) = make_float4(lo[0], lo[1], lo[2], lo[3]);
        *(float4*)(P + (mb + tm*4 + ip*2 + 1) * D_ + nb + tn*4) = make_float4(hi[0], hi[1], hi[2], hi[3]);
    }
}

// ---------------------------------------------------------------------------
// K2: score = D - 2*sum_d 1/(1+e^{2(q+v)}) using precomputed exponentials:
//     w = 2^-16 * (1 + EQ*EV) = fma(EQ, EV', 2^-16)  -- ONE FFMA2 per 2 elems.
// Quad-rational combine, rcp.approx pair, final scale by 2^-15.
// Tile: 128 qi x 32 jj per block, 256 threads, 8x(2-lane) per thread.
// ---------------------------------------------------------------------------
__global__ __launch_bounds__(256) void score_kernel()
{
    __shared__ float4 sQ[128 * 8];       // swizzled: r*8 + (vec ^ (r&7))
    __shared__ float  sVP[16 * 16 * 4];  // jj-paired EV' values

    const int tid = threadIdx.x;
    const int b   = blockIdx.y;
    const int qt  = blockIdx.x >> 4;     // 0..1  (TQ/128)
    const int jt  = blockIdx.x & 15;     // 0..15 (TV/32)
    const int qbase = qt * 128, jbase = jt * 32;
    const float* qp = g_qproj + (b * TQ + qbase) * D_;
    const float* vp = g_vproj + (b * TV + jbase) * D_;
    const int tq = tid >> 4, tj = tid & 15;

    const u64 C16 = bc2(0x1p-16f);

    u64 acc2[8] = {};   // lanes = (jj=jbase+tj, jj=jbase+16+tj), scaled by 2^16

    for (int dc = 0; dc < D_; dc += 32) {
        __syncthreads();
        #pragma unroll
        for (int i = 0; i < 4; i++) {          // Q: 128 rows x 8 vecs
            int idx = i * 256 + tid;
            int r = idx >> 3, vec = idx & 7;
            sQ[r*8 + (vec ^ (r & 7))] = *(const float4*)(qp + r * D_ + dc + vec * 4);
        }
        {                                       // V: 32 rows x 8 vecs, paired layout
            int r = tid >> 3, vec = tid & 7;
            float4 v = *(const float4*)(vp + r * D_ + dc + vec * 4);
            int half = r >> 4, row = r & 15;
            float* base0 = &sVP[((2*vec)   * 16 + row) * 4];
            float* base1 = &sVP[((2*vec+1) * 16 + row) * 4];
            base0[half]     = v.x;  base0[2 + half] = v.y;
            base1[half]     = v.z;  base1[2 + half] = v.w;
        }
        __syncthreads();

        #pragma unroll
        for (int vec = 0; vec < 8; vec++) {
            ulonglong2 vp01 = *(const ulonglong2*)&sVP[((2*vec)   * 16 + tj) * 4];
            ulonglong2 vp23 = *(const ulonglong2*)&sVP[((2*vec+1) * 16 + tj) * 4];
            #pragma unroll
            for (int a = 0; a < 8; a++) {
                int r = a*16 + tq;
                float4 q = sQ[r*8 + (vec ^ (r & 7))];
                u64 w0 = fma2(bc2(q.x), vp01.x, C16);
                u64 w1 = fma2(bc2(q.y), vp01.y, C16);
                u64 w2 = fma2(bc2(q.z), vp23.x, C16);
                u64 w3 = fma2(bc2(q.w), vp23.y, C16);
                u64 p12  = mul2(w0, w1);
                u64 p34  = mul2(w2, w3);
                u64 zs01 = add2(w0, w1);
                u64 zs23 = add2(w2, w3);
                u64 num  = fma2(p12, zs23, mul2(p34, zs01));
                u64 den  = mul2(p12, p34);
                u64 y    = rcp2_pair(den);
                acc2[a]  = fma2(num, y, acc2[a]);
            }
        }
    }

    #pragma unroll
    for (int a = 0; a < 8; a++) {
        float s0, s1; upk2(acc2[a], s0, s1);
        int qi = qbase + a*16 + tq;
        // score = D - 2 * (acc * 2^-16) = D - acc * 2^-15
        g_score[(b * TQ + qi) * TV + jbase + tj]      = (float)D_ - s0 * 0x1p-15f;
        g_score[(b * TQ + qi) * TV + jbase + 16 + tj] = (float)D_ - s1 * 0x1p-15f;
    }
}

// ---------------------------------------------------------------------------
// K3: softmax over TV=512 (16-row slab, warp per 2 rows) + transposed output.
// ---------------------------------------------------------------------------
__global__ __launch_bounds__(256) void softmax_kernel(float* __restrict__ out_at)
{
    __shared__ float sm[16][513];
    const int b    = blockIdx.x >> 4;
    const int slab = blockIdx.x & 15;
    const int q0   = slab * 16;
    const int wid  = threadIdx.x >> 5, lane = threadIdx.x & 31;

    #pragma unroll
    for (int rr = 0; rr < 2; rr++) {
        const int r = wid * 2 + rr;
        float* s = g_score + (size_t)(b * TQ + q0 + r) * TV;
        float4 v[4];
        #pragma unroll
        for (int k = 0; k < 4; k++) v[k] = *(const float4*)(s + (k*32 + lane)*4);
        float m = -1e30f;
        #pragma unroll
        for (int k = 0; k < 4; k++)
            m = fmaxf(m, fmaxf(fmaxf(v[k].x, v[k].y), fmaxf(v[k].z, v[k].w)));
        #pragma unroll
        for (int o = 16; o; o >>= 1) m = fmaxf(m, __shfl_xor_sync(0xffffffffu, m, o));

        float4 e[4]; float sum = 0.0f;
        #pragma unroll
        for (int k = 0; k < 4; k++) {
            e[k].x = fast_ex2((v[k].x - m) * LOG2E);
            e[k].y = fast_ex2((v[k].y - m) * LOG2E);
            e[k].z = fast_ex2((v[k].z - m) * LOG2E);
            e[k].w = fast_ex2((v[k].w - m) * LOG2E);
            sum += (e[k].x + e[k].y) + (e[k].z + e[k].w);
        }
        #pragma unroll
        for (int o = 16; o; o >>= 1) sum += __shfl_xor_sync(0xffffffffu, sum, o);
        float inv = 1.0f / sum;

        #pragma unroll
        for (int k = 0; k < 4; k++) {
            float4 a = make_float4(e[k].x*inv, e[k].y*inv, e[k].z*inv, e[k].w*inv);
            *(float4*)(s + (k*32 + lane)*4) = a;
            int col = (k*32 + lane)*4;
            sm[r][col+0] = a.x; sm[r][col+1] = a.y; sm[r][col+2] = a.z; sm[r][col+3] = a.w;
        }
    }
    __syncthreads();

    const int i = lane & 15;
    const int jb = wid * 64 + (lane >> 4) * 32;
    float* dst = out_at + (size_t)(b * TV) * TQ + q0 + i;
    #pragma unroll
    for (int jj = 0; jj < 32; jj++) {
        int j = jb + jj;
        dst[(size_t)j * TQ] = sm[i][j];
    }
}

// ---------------------------------------------------------------------------
// K4: context[b] = alignment[b] (256x512) @ value[b] (512x256), f32x2 inner.
// ---------------------------------------------------------------------------
__global__ __launch_bounds__(256) void context_kernel(
    const float* __restrict__ value, float* __restrict__ out)
{
    __shared__ float sAT[16][64];
    __shared__ float sB[16][64];
    const int tid = threadIdx.x;
    const int b  = blockIdx.z;
    const int mb = blockIdx.y * 64;
    const int nb = blockIdx.x * 64;
    const float* A = g_score + b * TQ * TV;
    const float* V = value + b * TV * D_;
    float* C = out + b * TQ * (2 * D_);
    const int tm = tid >> 4, tn = tid & 15;
    const int arow = tid >> 2, akv = tid & 3;
    const int brow = tid >> 4, bcv = tid & 15;

    u64 acc2[2][4] = {};

    for (int kt = 0; kt < TV; kt += 16) {
        float4 av = *(const float4*)(A + (mb + arow) * TV + kt + akv * 4);
        float4 bv = *(const float4*)(V + (kt + brow) * D_ + nb + bcv * 4);
        __syncthreads();
        sAT[akv*4+0][arow] = av.x; sAT[akv*4+1][arow] = av.y;
        sAT[akv*4+2][arow] = av.z; sAT[akv*4+3][arow] = av.w;
        *(float4*)&sB[brow][bcv*4] = bv;
        __syncthreads();
        #pragma unroll
        for (int k = 0; k < 16; k++) {
            float2 a01 = *(const float2*)&sAT[k][tm*4];
            float2 a23 = *(const float2*)&sAT[k][tm*4 + 2];
            float4 bq  = *(const float4*)&sB[k][tn*4];
            u64 A01 = pk2(a01.x, a01.y);
            u64 A23 = pk2(a23.x, a23.y);
            u64 B0 = bc2(bq.x), B1 = bc2(bq.y), B2 = bc2(bq.z), B3 = bc2(bq.w);
            acc2[0][0] = fma2(A01, B0, acc2[0][0]);
            acc2[0][1] = fma2(A01, B1, acc2[0][1]);
            acc2[0][2] = fma2(A01, B2, acc2[0][2]);
            acc2[0][3] = fma2(A01, B3, acc2[0][3]);
            acc2[1][0] = fma2(A23, B0, acc2[1][0]);
            acc2[1][1] = fma2(A23, B1, acc2[1][1]);
            acc2[1][2] = fma2(A23, B2, acc2[1][2]);
            acc2[1][3] = fma2(A23, B3, acc2[1][3]);
        }
    }
    #pragma unroll
    for (int ip = 0; ip < 2; ip++) {
        float lo[4], hi[4];
        #pragma unroll
        for (int j = 0; j < 4; j++) upk2(acc2[ip][j], lo[j], hi[j]);
        *(float4*)(C + (mb + tm*4 + ip*2 + 0) * (2 * D_) + nb + tn*4) = make_float4(lo[0], lo[1], lo[2], lo[3]);
        *(float4*)(C + (mb + tm*4 + ip*2 + 1) * (2 * D_) + nb + tn*4) = make_float4(hi[0], hi[1], hi[2], hi[3]);
    }
}

// ---------------------------------------------------------------------------
// K5: out[b][qi][D:2D] = query[b][qi][:]
// ---------------------------------------------------------------------------
__global__ __launch_bounds__(256) void copy_query_kernel(
    const float* __restrict__ query, float* __restrict__ out)
{
    int g = blockIdx.x * 256 + threadIdx.x;
    int row = g >> 6, vec = g & 63;
    ((float4*)out)[row * 128 + 64 + vec] = ((const float4*)query)[g];
}

// ---------------------------------------------------------------------------
extern "C" void kernel_launch(void* const* d_in, const int* in_sizes, int n_in,
                              void* d_out, int out_size)
{
    const float* query = (const float*)d_in[0];   // [8,256,256]
    const float* value = (const float*)d_in[1];   // [8,512,256]
    const float* W1    = (const float*)d_in[2];   // [256,256]
    const float* b1    = (const float*)d_in[3];   // [256]
    const float* W2    = (const float*)d_in[4];   // [256,256]
    const float* b2    = (const float*)d_in[5];   // [256]
    float* out = (float*)d_out;

    void *qp_, *vp_;
    cudaGetSymbolAddress(&qp_, g_qproj);
    cudaGetSymbolAddress(&vp_, g_vproj);

    proj_kernel<<<dim3(4, 32), 256>>>(query, W1, b1, (float*)qp_,  0.0f);
    proj_kernel<<<dim3(4, 64), 256>>>(value, W2, b2, (float*)vp_, -16.0f);
    score_kernel<<<dim3(32, 8), 256>>>();
    softmax_kernel<<<128, 256>>>(out + B_ * TQ * 2 * D_);
    context_kernel<<<dim3(4, 4, 8), 256>>>(value, out);
    copy_query_kernel<<<512, 256>>>(query, out);
}